// round 8
// baseline (speedup 1.0000x reference)
#include <cuda_runtime.h>
#include <math.h>

#define BB 16
#define DD 768
#define LL 96
#define CHUNK 128
#define NCHUNK 6
#define XPITCH 132   // 128 + 4 pad
#define SOFT_ELEMS (BB*LL*LL*DD)        // 113246208
#define HW_ELEMS   (BB*LL*LL*3)         // 442368
#define SMEM_FLOATS (LL*XPITCH + 2*LL + 2*192)
#define NINVALID (LL*(LL-1)/2)          // 4560 invalid (l,r) rows per b

__constant__ float c_posw[6] = {2.0f, 1.5f, 1.0f, 0.8f, 0.3f, 0.5f};
__constant__ float c_depw[6] = {2.0f, 1.5f, 1.5f, 1.2f, 1.0f, 0.5f};

__device__ float g_E[BB*LL];     // exp(base/TEMP) per token
__device__ float g_base[BB*LL];  // raw base score bits (XLA mul/add path)
__device__ float g_S[BB*DD];     // per-(b,d) column sum of embeds

// ---------------------------------------------------------------------------
// prep: warp-per-d coalesced column sums; block x==0 also does degree/E/base
// ---------------------------------------------------------------------------
__global__ void prep_kernel(const float* __restrict__ x, const int* __restrict__ par,
                            const int* __restrict__ pos, const int* __restrict__ dep) {
    int b = blockIdx.y;
    int tid = threadIdx.x;
    int w = tid >> 5, lane = tid & 31;
    int d = blockIdx.x * 8 + w;

    const float* p = x + ((size_t)b*DD + d)*LL;
    float s = p[lane] + p[lane + 32] + p[lane + 64];
#pragma unroll
    for (int off = 16; off; off >>= 1) s += __shfl_down_sync(0xffffffffu, s, off);
    if (lane == 0) g_S[b*DD + d] = s;

    if (blockIdx.x == 0) {
        __shared__ int cnt[LL];
        if (tid < LL) cnt[tid] = 0;
        __syncthreads();
        if (tid < LL) atomicAdd(&cnt[par[b*LL + tid]], 1);
        __syncthreads();
        if (tid < LL) {
            float t0 = __fmul_rn(1.5f, (float)cnt[tid]);
            float t1 = __fadd_rn(2.0f, t0);
            float t2 = __fadd_rn(t1, __fmul_rn(0.8f, c_posw[pos[b*LL + tid]]));
            float base = __fadd_rn(t2, __fmul_rn(0.5f, c_depw[dep[b*LL + tid]]));
            g_base[b*LL + tid] = base;
            g_E[b*LL + tid] = expf(base / 0.7f);
        }
    }
}

// ---------------------------------------------------------------------------
// per-warp center-chain walker, templated so non-aux slices carry no top-k code
// ---------------------------------------------------------------------------
template<bool AUX>
__device__ __forceinline__ void run_chain(
    const float* __restrict__ x_sm, const float* __restrict__ E_sm,
    const float* __restrict__ base_sm, const float* __restrict__ M2,
    const float* __restrict__ Mm,
    float* __restrict__ out, int b, int c2, int chunk, int lane)
{
    const int dlo = (lane << 2);
    const float* Sp = g_S + b*DD + chunk*CHUNK + dlo;
    float4 Sa = *(const float4*)Sp;

    int l = c2 >> 1;
    int r = c2 - l;
    int kl = c2 - 2*l;   // 0 or 1
    int kr = 2*r - c2;   // 0 or 1

    const float* xl = x_sm + l*XPITCH + dlo;
    const float* xr = x_sm + r*XPITCH + dlo;

    float4 A = make_float4(0.f,0.f,0.f,0.f);
    float za = 0.f;
    float y0 = -1e30f, y1 = -1e30f, y2 = -1e30f;
    int   i0 = 0x7fffffff, i1 = 0x7fffffff, i2 = 0x7fffffff;

    auto addtok = [&](int t, int k, const float* xrow) {
        float w = E_sm[t] * M2[k];
        if constexpr (AUX) {
            float y = __fadd_rn(base_sm[t], Mm[k]);   // JAX score bits (order key)
            bool c0 = (y > y0) || (y == y0 && t < i0);
            bool c1 = (y > y1) || (y == y1 && t < i1);
            bool c2b = (y > y2) || (y == y2 && t < i2);
            if (c0)      { y2=y1; i2=i1; y1=y0; i1=i0; y0=y; i0=t; }
            else if (c1) { y2=y1; i2=i1; y1=y; i1=t; }
            else if (c2b){ y2=y;  i2=t; }
        }
        float a = w - 1.0f;
        za += a;
        float4 xa = *(const float4*)xrow;
        A.x += a*xa.x; A.y += a*xa.y; A.z += a*xa.z; A.w += a*xa.w;
    };

    addtok(l, kl, xl);
    if (r != l) addtok(r, kr, xr);

    float* o = out + ((size_t)((b*LL + l)*LL + r))*DD + chunk*CHUNK + dlo;
    float* hw = out + SOFT_ELEMS + (size_t)((b*LL + l)*LL + r)*3;
    float* hi = hw + HW_ELEMS;
    const ptrdiff_t ODELTA = -(ptrdiff_t)(LL-1)*DD;
    const ptrdiff_t HDELTA = -(ptrdiff_t)(LL-1)*3;

    while (1) {
        float invZ = 1.0f / ((float)LL + za);
        float4 o0;
        o0.x = (A.x + Sa.x)*invZ; o0.y = (A.y + Sa.y)*invZ;
        o0.z = (A.z + Sa.z)*invZ; o0.w = (A.w + Sa.w)*invZ;
        __stcs((float4*)o, o0);

        if constexpr (AUX) {
            if (lane == 0) {
                int len = r - l + 1;
                int k0 = 2*i0 - c2; k0 = k0 < 0 ? -k0 : k0;
                float w0 = E_sm[i0] * M2[k0];
                float hv1, hv2, fi1, fi2;
                if (len >= 3) {
                    int k1 = 2*i1 - c2; k1 = k1 < 0 ? -k1 : k1;
                    int k2v = 2*i2 - c2; k2v = k2v < 0 ? -k2v : k2v;
                    hv1 = E_sm[i1]*M2[k1]*invZ;  fi1 = (float)i1;
                    hv2 = E_sm[i2]*M2[k2v]*invZ; fi2 = (float)i2;
                } else if (len == 2) {
                    int k1 = 2*i1 - c2; k1 = k1 < 0 ? -k1 : k1;
                    hv1 = E_sm[i1]*M2[k1]*invZ;  fi1 = (float)i1;
                    hv2 = invZ;                  fi2 = (l > 0) ? 0.f : (float)(r+1);
                } else {
                    hv1 = invZ; hv2 = invZ;
                    if (l == 0)      { fi1 = 1.f; fi2 = 2.f; }
                    else if (l == 1) { fi1 = 0.f; fi2 = 2.f; }
                    else             { fi1 = 0.f; fi2 = 1.f; }
                }
                hw[0] = w0*invZ; hw[1] = hv1; hw[2] = hv2;
                hi[0] = (float)i0; hi[1] = fi1; hi[2] = fi2;
            }
        }

        if (l == 0 || r == LL-1) break;
        --l; ++r; kl += 2; kr += 2;
        xl -= XPITCH; xr += XPITCH;
        addtok(l, kl, xl);
        addtok(r, kr, xr);
        o += ODELTA;
        if constexpr (AUX) { hw += HDELTA; hi += HDELTA; }
    }
}

// ---------------------------------------------------------------------------
// fused kernel, balanced: grid (6, NCHUNK, 16) = 576 CTAs = one wave @4/SM.
// warp q = blockIdx.x*8+wid owns chain quadruple {q,190-q,94-q,96+q} (96-98
// spans each; q=47 -> {47,143,95}=96), then strides the 4560 invalid rows
// (j += 48) writing zeros in its d-chunk slice (+ aux on chunk 0).
// ---------------------------------------------------------------------------
__global__ void __launch_bounds__(256, 4)
span_kernel(const float* __restrict__ x, float* __restrict__ out, int write_aux) {
    int g = blockIdx.x, chunk = blockIdx.y, b = blockIdx.z;
    int tid = threadIdx.x;

    extern __shared__ float sm[];
    float* x_sm    = sm;                   // [96][132]
    float* E_sm    = sm + LL*XPITCH;       // [96]
    float* base_sm = E_sm + LL;            // [96]
    float* M2      = base_sm + LL;         // [192]
    float* Mm      = M2 + 192;             // [192]

    const float* gx = x + ((size_t)b*DD + (size_t)chunk*CHUNK)*LL;
    for (int i = tid; i < CHUNK*LL; i += 256) {
        int d = i / LL;
        int t = i - d*LL;
        x_sm[t*XPITCH + d] = gx[i];
    }
    for (int k = tid; k < 191; k += 256) {
        float denom = __fadd_rn(1.0f, 0.5f*(float)k);   // exact
        float med = __fdiv_rn(0.5f, denom);             // == JAX medoid bits
        Mm[k] = med;
        M2[k] = expf(med / 0.7f);
    }
    if (tid < LL) {
        E_sm[tid]    = g_E[b*LL + tid];
        base_sm[tid] = g_base[b*LL + tid];
    }
    __syncthreads();

    int wid = tid >> 5, lane = tid & 31;
    int q = g*8 + wid;                      // 0..47
    bool aux = (chunk == 0) && write_aux;

    int c2s[4];
    if (q < 47) { c2s[0] = q; c2s[1] = 190 - q; c2s[2] = 94 - q; c2s[3] = 96 + q; }
    else        { c2s[0] = 47; c2s[1] = 143;    c2s[2] = 95;     c2s[3] = -1; }

#pragma unroll
    for (int i = 0; i < 4; i++) {
        int c2 = c2s[i];
        if (c2 < 0) break;
        if (aux) run_chain<true >(x_sm, E_sm, base_sm, M2, Mm, out, b, c2, chunk, lane);
        else     run_chain<false>(x_sm, E_sm, base_sm, M2, Mm, out, b, c2, chunk, lane);
    }

    // ---- zero-fill duty: invalid rows j = q, q+48, ... of triangular enum ----
    const int dlo = (lane << 2);
    float4 z = make_float4(0.f, 0.f, 0.f, 0.f);
    for (int j = q; j < NINVALID; j += 48) {
        int l = (int)((1.0f + sqrtf(8.0f*(float)j + 1.0f)) * 0.5f);
        while (l*(l-1)/2 > j) l--;
        while (l*(l+1)/2 <= j) l++;
        int r = j - l*(l-1)/2;               // r in [0, l)
        size_t row = (size_t)(b*LL + l)*LL + r;
        __stcs((float4*)(out + row*DD + chunk*CHUNK + dlo), z);
        if (aux) {
            float* hw = out + SOFT_ELEMS + row*3;
            float* hi = hw + HW_ELEMS;
            if (lane < 3)      hw[lane] = 0.f;
            else if (lane < 6) hi[lane-3] = -1.f;
        }
    }
}

// ---------------------------------------------------------------------------
extern "C" void kernel_launch(void* const* d_in, const int* in_sizes, int n_in,
                              void* d_out, int out_size) {
    const float* x  = (const float*)d_in[0];
    const int* par  = (const int*)d_in[1];
    const int* pos  = (const int*)d_in[2];
    const int* dep  = (const int*)d_in[3];
    float* out = (float*)d_out;

    int write_aux = (out_size >= SOFT_ELEMS + 2*HW_ELEMS) ? 1 : 0;

    prep_kernel<<<dim3(DD/8, BB), 256>>>(x, par, pos, dep);

    int smem = SMEM_FLOATS * 4;
    cudaFuncSetAttribute(span_kernel, cudaFuncAttributeMaxDynamicSharedMemorySize, smem);
    span_kernel<<<dim3(6, NCHUNK, BB), 256, smem>>>(x, out, write_aux);
}

// round 9
// speedup vs baseline: 1.2676x; 1.2676x over previous
#include <cuda_runtime.h>

#define BB 16
#define DD 768
#define LL 96
#define CHUNK 128
#define NCHUNK 6
#define XPITCH 132   // 128 + 4 pad
#define SOFT_ELEMS (BB*LL*LL*DD)        // 113246208
#define HW_ELEMS   (BB*LL*LL*3)         // 442368
#define SMEM_FLOATS (LL*XPITCH + 2*LL + 2*192)

__constant__ float c_posw[6] = {2.0f, 1.5f, 1.0f, 0.8f, 0.3f, 0.5f};
__constant__ float c_depw[6] = {2.0f, 1.5f, 1.5f, 1.2f, 1.0f, 0.5f};

__device__ float g_E[BB*LL];     // exp(base/TEMP) per token
__device__ float g_base[BB*LL];  // raw base score bits (XLA mul/add path)
__device__ float g_S[BB*DD];     // per-(b,d) column sum of embeds

// ---------------------------------------------------------------------------
// prep: warp-per-d coalesced column sums; block x==0 also does degree/E/base
// ---------------------------------------------------------------------------
__global__ void prep_kernel(const float* __restrict__ x, const int* __restrict__ par,
                            const int* __restrict__ pos, const int* __restrict__ dep) {
    int b = blockIdx.y;
    int tid = threadIdx.x;
    int w = tid >> 5, lane = tid & 31;
    int d = blockIdx.x * 8 + w;

    const float* p = x + ((size_t)b*DD + d)*LL;
    float s = p[lane] + p[lane + 32] + p[lane + 64];
#pragma unroll
    for (int off = 16; off; off >>= 1) s += __shfl_down_sync(0xffffffffu, s, off);
    if (lane == 0) g_S[b*DD + d] = s;

    if (blockIdx.x == 0) {
        __shared__ int cnt[LL];
        if (tid < LL) cnt[tid] = 0;
        __syncthreads();
        if (tid < LL) atomicAdd(&cnt[par[b*LL + tid]], 1);
        __syncthreads();
        if (tid < LL) {
            float t0 = __fmul_rn(1.5f, (float)cnt[tid]);
            float t1 = __fadd_rn(2.0f, t0);
            float t2 = __fadd_rn(t1, __fmul_rn(0.8f, c_posw[pos[b*LL + tid]]));
            float base = __fadd_rn(t2, __fmul_rn(0.5f, c_depw[dep[b*LL + tid]]));
            g_base[b*LL + tid] = base;
            g_E[b*LL + tid] = expf(base / 0.7f);
        }
    }
}

// ---------------------------------------------------------------------------
// per-warp center-chain walker, templated so non-aux slices carry no top-k code
// ---------------------------------------------------------------------------
template<bool AUX>
__device__ __forceinline__ void run_chain(
    const float* __restrict__ x_sm, const float* __restrict__ E_sm,
    const float* __restrict__ base_sm, const float* __restrict__ M2,
    const float* __restrict__ Mm,
    float* __restrict__ out, int b, int c2, int chunk, int lane)
{
    const int dlo = (lane << 2);
    const float* Sp = g_S + b*DD + chunk*CHUNK + dlo;
    float4 Sa = *(const float4*)Sp;

    int l = c2 >> 1;
    int r = c2 - l;
    int kl = c2 - 2*l;   // 0 or 1
    int kr = 2*r - c2;   // 0 or 1

    const float* xl = x_sm + l*XPITCH + dlo;
    const float* xr = x_sm + r*XPITCH + dlo;

    float4 A = make_float4(0.f,0.f,0.f,0.f);
    float za = 0.f;
    float y0 = -1e30f, y1 = -1e30f, y2 = -1e30f;
    int   i0 = 0x7fffffff, i1 = 0x7fffffff, i2 = 0x7fffffff;

    auto addtok = [&](int t, int k, const float* xrow) {
        float w = E_sm[t] * M2[k];
        if constexpr (AUX) {
            float y = __fadd_rn(base_sm[t], Mm[k]);   // JAX score bits (order key)
            bool c0 = (y > y0) || (y == y0 && t < i0);
            bool c1 = (y > y1) || (y == y1 && t < i1);
            bool c2b = (y > y2) || (y == y2 && t < i2);
            if (c0)      { y2=y1; i2=i1; y1=y0; i1=i0; y0=y; i0=t; }
            else if (c1) { y2=y1; i2=i1; y1=y; i1=t; }
            else if (c2b){ y2=y;  i2=t; }
        }
        float a = w - 1.0f;
        za += a;
        float4 xa = *(const float4*)xrow;
        A.x += a*xa.x; A.y += a*xa.y; A.z += a*xa.z; A.w += a*xa.w;
    };

    addtok(l, kl, xl);
    if (r != l) addtok(r, kr, xr);

    float* o = out + ((size_t)((b*LL + l)*LL + r))*DD + chunk*CHUNK + dlo;
    float* hw = out + SOFT_ELEMS + (size_t)((b*LL + l)*LL + r)*3;
    float* hi = hw + HW_ELEMS;
    const ptrdiff_t ODELTA = -(ptrdiff_t)(LL-1)*DD;
    const ptrdiff_t HDELTA = -(ptrdiff_t)(LL-1)*3;

    while (1) {
        float invZ = __fdividef(1.0f, (float)LL + za);   // MUFU.RCP path
        float4 o0;
        o0.x = (A.x + Sa.x)*invZ; o0.y = (A.y + Sa.y)*invZ;
        o0.z = (A.z + Sa.z)*invZ; o0.w = (A.w + Sa.w)*invZ;
        __stcs((float4*)o, o0);

        if constexpr (AUX) {
            if (lane == 0) {
                int len = r - l + 1;
                int k0 = 2*i0 - c2; k0 = k0 < 0 ? -k0 : k0;
                float w0 = E_sm[i0] * M2[k0];
                float hv1, hv2, fi1, fi2;
                if (len >= 3) {
                    int k1 = 2*i1 - c2; k1 = k1 < 0 ? -k1 : k1;
                    int k2v = 2*i2 - c2; k2v = k2v < 0 ? -k2v : k2v;
                    hv1 = E_sm[i1]*M2[k1]*invZ;  fi1 = (float)i1;
                    hv2 = E_sm[i2]*M2[k2v]*invZ; fi2 = (float)i2;
                } else if (len == 2) {
                    int k1 = 2*i1 - c2; k1 = k1 < 0 ? -k1 : k1;
                    hv1 = E_sm[i1]*M2[k1]*invZ;  fi1 = (float)i1;
                    hv2 = invZ;                  fi2 = (l > 0) ? 0.f : (float)(r+1);
                } else {
                    hv1 = invZ; hv2 = invZ;
                    if (l == 0)      { fi1 = 1.f; fi2 = 2.f; }
                    else if (l == 1) { fi1 = 0.f; fi2 = 2.f; }
                    else             { fi1 = 0.f; fi2 = 1.f; }
                }
                hw[0] = w0*invZ; hw[1] = hv1; hw[2] = hv2;
                hi[0] = (float)i0; hi[1] = fi1; hi[2] = fi2;
            }
        }

        if (l == 0 || r == LL-1) break;
        --l; ++r; kl += 2; kr += 2;
        xl -= XPITCH; xr += XPITCH;
        addtok(l, kl, xl);
        addtok(r, kr, xr);
        o += ODELTA;
        if constexpr (AUX) { hw += HDELTA; hi += HDELTA; }
    }
}

// ---------------------------------------------------------------------------
// fused kernel: grid (12, 8, 16)
//   blockIdx.y in {0,1}: dedicated zero-fill CTAs (launched FIRST — longest)
//                        unit z = y*12+g in [0,24); rows l = z, z+24, ...
//   blockIdx.y in [2,8): span chains for d-chunk (y-2); warp u = g*8+wid
//                        owns balanced pair {u, 96+u} (48-49 spans total)
// ---------------------------------------------------------------------------
__global__ void __launch_bounds__(256, 4)
span_kernel(const float* __restrict__ x, float* __restrict__ out, int write_aux) {
    int g = blockIdx.x, yb = blockIdx.y, b = blockIdx.z;
    int tid = threadIdx.x;

    if (yb < 2) {
        // ---- streaming zero-fill: l = z, z+24, z+48, z+72 ----
        int z = yb*12 + g;   // [0,24)
        float4 zz = make_float4(0.f, 0.f, 0.f, 0.f);
        for (int l = z; l < LL; l += 24) {
            if (l == 0) continue;
            float4* p = (float4*)(out + (size_t)(b*LL + l)*LL*DD);
            int n4 = l * (DD/4);
            for (int i = tid; i < n4; i += 256) __stcs(p + i, zz);
            if (write_aux) {
                float* hw = out + SOFT_ELEMS + (size_t)(b*LL + l)*LL*3;
                float* hi = hw + HW_ELEMS;
                int n = l*3;
                for (int i = tid; i < n; i += 256) hw[i] = 0.f;
                for (int i = tid; i < n; i += 256) hi[i] = -1.f;
            }
        }
        return;
    }

    int chunk = yb - 2;
    extern __shared__ float sm[];
    float* x_sm    = sm;                   // [96][132]
    float* E_sm    = sm + LL*XPITCH;       // [96]
    float* base_sm = E_sm + LL;            // [96]
    float* M2      = base_sm + LL;         // [192]
    float* Mm      = M2 + 192;             // [192]

    const float* gx = x + ((size_t)b*DD + (size_t)chunk*CHUNK)*LL;
    for (int i = tid; i < CHUNK*LL; i += 256) {
        int d = i / LL;
        int t = i - d*LL;
        x_sm[t*XPITCH + d] = gx[i];
    }
    for (int k = tid; k < 191; k += 256) {
        float denom = __fadd_rn(1.0f, 0.5f*(float)k);   // exact
        float med = __fdiv_rn(0.5f, denom);             // == JAX medoid bits
        Mm[k] = med;
        M2[k] = expf(med / 0.7f);
    }
    if (tid < LL) {
        E_sm[tid]    = g_E[b*LL + tid];
        base_sm[tid] = g_base[b*LL + tid];
    }
    __syncthreads();

    int wid = tid >> 5, lane = tid & 31;
    int u = g*8 + wid;                      // [0,96)
    bool aux = (chunk == 0) && write_aux;

    if (aux) {
        run_chain<true >(x_sm, E_sm, base_sm, M2, Mm, out, b, u, chunk, lane);
        if (u < 95)
            run_chain<true >(x_sm, E_sm, base_sm, M2, Mm, out, b, 96 + u, chunk, lane);
    } else {
        run_chain<false>(x_sm, E_sm, base_sm, M2, Mm, out, b, u, chunk, lane);
        if (u < 95)
            run_chain<false>(x_sm, E_sm, base_sm, M2, Mm, out, b, 96 + u, chunk, lane);
    }
}

// ---------------------------------------------------------------------------
extern "C" void kernel_launch(void* const* d_in, const int* in_sizes, int n_in,
                              void* d_out, int out_size) {
    const float* x  = (const float*)d_in[0];
    const int* par  = (const int*)d_in[1];
    const int* pos  = (const int*)d_in[2];
    const int* dep  = (const int*)d_in[3];
    float* out = (float*)d_out;

    int write_aux = (out_size >= SOFT_ELEMS + 2*HW_ELEMS) ? 1 : 0;

    prep_kernel<<<dim3(DD/8, BB), 256>>>(x, par, pos, dep);

    int smem = SMEM_FLOATS * 4;
    cudaFuncSetAttribute(span_kernel, cudaFuncAttributeMaxDynamicSharedMemorySize, smem);
    span_kernel<<<dim3(12, 8, BB), 256, smem>>>(x, out, write_aux);
}